// round 17
// baseline (speedup 1.0000x reference)
#include <cuda_runtime.h>
#include <cuda_fp16.h>
#include <cstdint>

// Problem constants
#define B_  2
#define S_  2048
#define E_  1024
#define H_  16
#define DH_ 64
#define HD_ 1024          // H*Dh
#define M_  (B_*S_)       // 4096 rows for all GEMMs
#define K_GEMM 1024
#define N_GEMM 1024

// ---------------------------------------------------------------------------
// Scratch (no cudaMalloc allowed)
// ---------------------------------------------------------------------------
__device__ __half g_Zh[M_ * K_GEMM];            // attention output
__device__ __half g_Wt[4 * N_GEMM * K_GEMM];    // 4 transposed weights [N][K]
__device__ __half g_Qh[M_ * HD_];
__device__ __half g_Kh[M_ * HD_];
__device__ __half g_Vh[M_ * HD_];

struct QkvArgs {
    const float* A[3];     // fp32 inputs (converted inline in MODE 0)
    const float* bias[3];
    __half* O[3];
};
struct PrepArgs { const float* W[4]; };

__device__ __forceinline__ uint32_t smem_u32(const void* p) {
    uint32_t a;
    asm("{ .reg .u64 t; cvta.to.shared.u64 t, %1; cvt.u32.u64 %0, t; }" : "=r"(a) : "l"(p));
    return a;
}
__device__ __forceinline__ float ex2f(float x) {
    float y;
    asm("ex2.approx.ftz.f32 %0, %1;" : "=f"(y) : "f"(x));
    return y;
}
__device__ __forceinline__ uint32_t pack_h2(float a, float b) {
    __half2 t = __floats2half2_rn(a, b);
    return *reinterpret_cast<uint32_t*>(&t);
}
__device__ __forceinline__ uint4 cvt8h(float4 a, float4 b) {
    uint4 r;
    r.x = pack_h2(a.x, a.y); r.y = pack_h2(a.z, a.w);
    r.z = pack_h2(b.x, b.y); r.w = pack_h2(b.z, b.w);
    return r;
}

#define CP_ASYNC16(dst, src) \
    asm volatile("cp.async.cg.shared.global [%0], [%1], 16;" :: "r"(dst), "l"(src))
#define CP_COMMIT() asm volatile("cp.async.commit_group;" ::: "memory")
#define CP_WAIT(n)  asm volatile("cp.async.wait_group %0;" :: "n"(n) : "memory")

#define LDSM4(r0, r1, r2, r3, addr) \
    asm volatile("ldmatrix.sync.aligned.m8n8.x4.shared.b16 {%0,%1,%2,%3}, [%4];" \
                 : "=r"(r0), "=r"(r1), "=r"(r2), "=r"(r3) : "r"(addr))
#define LDSM4T(r0, r1, r2, r3, addr) \
    asm volatile("ldmatrix.sync.aligned.m8n8.x4.trans.shared.b16 {%0,%1,%2,%3}, [%4];" \
                 : "=r"(r0), "=r"(r1), "=r"(r2), "=r"(r3) : "r"(addr))
#define MMAH(d, a, b) \
    asm volatile("mma.sync.aligned.m16n8k16.row.col.f32.f16.f16.f32 " \
                 "{%0,%1,%2,%3}, {%4,%5,%6,%7}, {%8,%9}, {%0,%1,%2,%3};" \
                 : "+f"((d)[0]), "+f"((d)[1]), "+f"((d)[2]), "+f"((d)[3]) \
                 : "r"((a)[0]), "r"((a)[1]), "r"((a)[2]), "r"((a)[3]), \
                   "r"((b)[0]), "r"((b)[1]))

// ---------------------------------------------------------------------------
// Weight prep (batched): W[K][N] fp32 -> Wt[z] [N][K] fp16 (transpose)
// grid 4096, block (32,8)
// ---------------------------------------------------------------------------
__global__ void __launch_bounds__(256)
prep_w_kernel(PrepArgs pa, __half* __restrict__ wt)
{
    __shared__ float t[32][33];
    int pid = blockIdx.x;
    int z = pid >> 10;
    int idx = pid & 1023;
    int n0 = (idx & 31) * 32, k0 = (idx >> 5) * 32;
    int tx = threadIdx.x, ty = threadIdx.y;
    const float* W = pa.W[z];
    const size_t zoff = (size_t)z * N_GEMM * K_GEMM;
    #pragma unroll
    for (int i = 0; i < 4; i++)
        t[ty + 8 * i][tx] = W[(size_t)(k0 + ty + 8 * i) * N_GEMM + n0 + tx];
    __syncthreads();
    #pragma unroll
    for (int i = 0; i < 4; i++) {
        float v = t[tx][ty + 8 * i];
        wt[zoff + (size_t)(n0 + ty + 8 * i) * K_GEMM + k0 + tx] = __float2half_rn(v);
    }
}

// ---------------------------------------------------------------------------
// HMMA fp16 GEMM, 3-stage ring, 2 CTAs/SM, ONE barrier/chunk,
// SMEM-staged coalesced epilogue. (unchanged from R14)
// ---------------------------------------------------------------------------
#define LDP 80
#define TILE_B (128 * LDP)      // 10240
#define STAGE_B (2 * TILE_B)    // 20480 (A | W)
#define NSTAGE 3
#define EPI_LDH 272
#define EPI_LDF 528

template<int MODE>
__global__ void __launch_bounds__(256, 2)
gemm_h_pipe(QkvArgs qa,
            const __half* __restrict__ Ah_,
            const __half* __restrict__ Wbase,
            const float* __restrict__ biasO,
            float* __restrict__ Cout)
{
    extern __shared__ __align__(16) char smem[];
    const uint32_t sb = smem_u32(smem);
    const int z = blockIdx.z;
    const int tid = threadIdx.x;
    const int wid = tid >> 5, lane = tid & 31;
    const int n0 = blockIdx.x * 128, m0 = blockIdx.y * 128;
    const int mw = (wid & 3) * 32;
    const int nw = (wid >> 2) * 64;

    const size_t woff = (MODE == 0 ? (size_t)z : (size_t)3) * N_GEMM * K_GEMM;
    const __half* gW = Wbase + woff + (size_t)n0 * K_GEMM;
    const float* gAf = (MODE == 0) ? qa.A[z] + (size_t)m0 * K_GEMM : nullptr;
    const __half* gAh = (MODE == 1) ? Ah_ + (size_t)m0 * K_GEMM : nullptr;

    float acc[2][8][4];
    #pragma unroll
    for (int mi = 0; mi < 2; mi++)
        #pragma unroll
        for (int ni = 0; ni < 8; ni++)
            #pragma unroll
            for (int r = 0; r < 4; r++) acc[mi][ni][r] = 0.f;

    const int row_[2] = { tid >> 2, (tid + 256) >> 2 };
    const int cc_[2]  = { tid & 3, (tid + 256) & 3 };

    float4 pfA[2][2];

    auto ldgA = [&](int c) {
        if (MODE == 0) {
            int k0 = c * 32;
            #pragma unroll
            for (int t = 0; t < 2; t++) {
                size_t go = (size_t)row_[t] * K_GEMM + k0 + cc_[t] * 8;
                pfA[t][0] = *(const float4*)&gAf[go];
                pfA[t][1] = *(const float4*)&gAf[go + 4];
            }
        }
    };
    auto stsA = [&](int c) {
        if (MODE == 0) {
            uint32_t base = (c % NSTAGE) * STAGE_B;
            #pragma unroll
            for (int t = 0; t < 2; t++) {
                uint32_t so = row_[t] * LDP + cc_[t] * 16;
                *(uint4*)(smem + base + so) = cvt8h(pfA[t][0], pfA[t][1]);
            }
        }
    };
    auto cpChunk = [&](int c) {
        uint32_t base = sb + (c % NSTAGE) * STAGE_B;
        int k0 = c * 32;
        #pragma unroll
        for (int t = 0; t < 2; t++) {
            uint32_t so = row_[t] * LDP + cc_[t] * 16;
            size_t go = (size_t)row_[t] * K_GEMM + k0 + cc_[t] * 8;
            if (MODE == 1) CP_ASYNC16(base + 0 * TILE_B + so, gAh + go);
            CP_ASYNC16(base + 1 * TILE_B + so, gW + go);
        }
        CP_COMMIT();
    };

    const uint32_t a_row = mw + (lane & 15);
    const uint32_t a_kadd = (lane >> 4) << 4;
    const uint32_t b_rowbase = nw + (lane & 7) + (((lane >> 4) & 1) << 3);
    const uint32_t b_kadd = ((lane >> 3) & 1) << 4;

    const int NCHUNK = K_GEMM / 32;
    ldgA(0);
    cpChunk(0);
    cpChunk(1);
    stsA(0);
    ldgA(1);

    for (int c = 0; c < NCHUNK; c++) {
        if (c + 1 < NCHUNK) { CP_WAIT(1); } else { CP_WAIT(0); }
        __syncthreads();

        const uint32_t stg = sb + (c % NSTAGE) * STAGE_B;
        const uint32_t sA = stg, sW = stg + TILE_B;

        #pragma unroll
        for (int s = 0; s < 2; s++) {
            const uint32_t kb = s * 32;
            uint32_t af[2][4];
            #pragma unroll
            for (int mi = 0; mi < 2; mi++)
                LDSM4(af[mi][0], af[mi][1], af[mi][2], af[mi][3],
                      sA + (a_row + mi * 16) * LDP + kb + a_kadd);
            uint32_t bf[8][2];
            #pragma unroll
            for (int g = 0; g < 4; g++)
                LDSM4(bf[2*g][0], bf[2*g][1], bf[2*g+1][0], bf[2*g+1][1],
                      sW + (b_rowbase + g * 16) * LDP + kb + b_kadd);
            #pragma unroll
            for (int mi = 0; mi < 2; mi++)
                #pragma unroll
                for (int ni = 0; ni < 8; ni++)
                    MMAH(acc[mi][ni], af[mi], bf[ni]);
        }
        if (c + 1 < NCHUNK) stsA(c + 1);
        if (c + 2 < NCHUNK) { ldgA(c + 2); cpChunk(c + 2); }
    }

    // ---- epilogue: SMEM-staged, coalesced 16B stores ----
    const float* bias = (MODE == 0) ? qa.bias[z] : biasO;
    const int rl = (lane >> 2);
    const int cl = nw + (lane & 3) * 2;

    __syncthreads();

    if (MODE == 0) {
        #pragma unroll
        for (int mi = 0; mi < 2; mi++) {
            #pragma unroll
            for (int ni = 0; ni < 8; ni++) {
                int col = cl + ni * 8;
                float b0 = bias[n0 + col], b1 = bias[n0 + col + 1];
                int r0l = mw + mi * 16 + rl;
                *(uint32_t*)(smem + r0l * EPI_LDH + col * 2) =
                    pack_h2(acc[mi][ni][0] + b0, acc[mi][ni][1] + b1);
                *(uint32_t*)(smem + (r0l + 8) * EPI_LDH + col * 2) =
                    pack_h2(acc[mi][ni][2] + b0, acc[mi][ni][3] + b1);
            }
        }
        __syncthreads();
        __half* Co = qa.O[z];
        #pragma unroll
        for (int t = 0; t < 8; t++) {
            int idx = tid + t * 256;
            int row = idx >> 4, seg = idx & 15;
            *(uint4*)&Co[(size_t)(m0 + row) * N_GEMM + n0 + seg * 8] =
                *(uint4*)(smem + row * EPI_LDH + seg * 16);
        }
    } else {
        #pragma unroll
        for (int pass = 0; pass < 2; pass++) {
            if (pass) __syncthreads();
            if ((mw >> 6) == pass) {
                int mwl = mw & 63;
                #pragma unroll
                for (int mi = 0; mi < 2; mi++) {
                    #pragma unroll
                    for (int ni = 0; ni < 8; ni++) {
                        int col = cl + ni * 8;
                        float b0 = bias[n0 + col], b1 = bias[n0 + col + 1];
                        int r0l = mwl + mi * 16 + rl;
                        float2 v0 = { acc[mi][ni][0] + b0, acc[mi][ni][1] + b1 };
                        float2 v1 = { acc[mi][ni][2] + b0, acc[mi][ni][3] + b1 };
                        *(float2*)(smem + r0l * EPI_LDF + col * 4) = v0;
                        *(float2*)(smem + (r0l + 8) * EPI_LDF + col * 4) = v1;
                    }
                }
            }
            __syncthreads();
            #pragma unroll
            for (int t = 0; t < 8; t++) {
                int idx = tid + t * 256;
                int row = idx >> 5, seg = idx & 31;
                *(uint4*)&Cout[(size_t)(m0 + pass * 64 + row) * N_GEMM + n0 + seg * 4] =
                    *(uint4*)(smem + row * EPI_LDF + seg * 16);
            }
        }
    }
}

// ---------------------------------------------------------------------------
// HMMA fp16 flash attention, causal. Q-TILE 64 ROWS, 128 threads (4 warps),
// 4 CTAs/SM -> halved critical chain per CTA. 3-stage cp.async K/V ring,
// ONE barrier/tile, heavy-CTA-first, warp-vote rescale skip, coalesced Z.
// grid (S/64 = 32, H, B) = 1024 CTAs. SMEM/CTA = 3 x 18432 = 55296.
// ---------------------------------------------------------------------------
#define LDK 144
#define AT_STAGE 18432
#define OF_K 0
#define OF_V 9216
#define EPI_LDZ 144

__global__ void __launch_bounds__(128, 4)
flash_attn_mma(const __half* __restrict__ Qh, const __half* __restrict__ Kh,
               const __half* __restrict__ Vh, __half* __restrict__ Zh)
{
    extern __shared__ __align__(16) char sm[];
    const uint32_t sb = smem_u32(sm);
    const int tid = threadIdx.x, wid = tid >> 5, lane = tid & 31;
    const int b = blockIdx.z, h = blockIdx.y;
    const int qt = gridDim.x - 1 - blockIdx.x;      // heavy CTAs first
    const int q0 = qt * 64;
    const size_t hb = (size_t)b * S_ * HD_ + h * DH_;

    const uint32_t arow = wid * 16 + (lane & 15);
    const uint32_t akadd = (lane >> 4) << 4;

    // Stage Q (64 rows x 128B) through stage-0 region via cp.async.
    #pragma unroll
    for (int t = 0; t < 4; t++) {
        int idx = tid + t * 128; int row = idx >> 3, cc = idx & 7;
        CP_ASYNC16(sb + row * LDK + cc * 16,
                   Qh + hb + (size_t)(q0 + row) * HD_ + cc * 8);
    }
    CP_COMMIT(); CP_WAIT(0);
    __syncthreads();
    uint32_t q[4][4];
    #pragma unroll
    for (int ks = 0; ks < 4; ks++)
        LDSM4(q[ks][0], q[ks][1], q[ks][2], q[ks][3],
              sb + arow * LDK + ks * 32 + akadd);
    __syncthreads();   // all warps done reading Q; stage 0 free

    auto issue_tile = [&](int kt) {
        uint32_t base = sb + (kt % 3) * AT_STAGE;
        int k0 = kt * 64;
        #pragma unroll
        for (int t = 0; t < 4; t++) {
            int idx = tid + t * 128; int row = idx >> 3, cc = idx & 7;
            size_t g = hb + (size_t)(k0 + row) * HD_ + cc * 8;
            uint32_t so = row * LDK + cc * 16;
            CP_ASYNC16(base + OF_K + so, Kh + g);
            CP_ASYNC16(base + OF_V + so, Vh + g);
        }
    };

    float o[8][4];
    #pragma unroll
    for (int i = 0; i < 8; i++)
        #pragma unroll
        for (int j = 0; j < 4; j++) o[i][j] = 0.f;
    float m0 = -1e30f, m1 = -1e30f, l0 = 0.f, l1 = 0.f;

    const uint32_t browbase = (lane & 7) + (((lane >> 4) & 1) << 3);
    const uint32_t bkadd = ((lane >> 3) & 1) << 4;
    const uint32_t vrow = lane & 15;
    const uint32_t vnadd = (lane >> 4) << 4;
    const float alpha = 0.125f * 1.4426950408889634f;   // 1/sqrt(64) * log2(e)
    const int rowg = q0 + wid * 16 + (lane >> 2);

    const int nt = qt + 1;    // 64-key tiles (>= 1)
    issue_tile(0); CP_COMMIT();
    if (nt > 1) { issue_tile(1); CP_COMMIT(); }
    else        { CP_COMMIT(); }   // keep group count consistent

    for (int kt = 0; kt < nt; kt++) {
        if (kt + 1 < nt) { CP_WAIT(1); } else { CP_WAIT(0); }
        __syncthreads();       // single barrier per tile
        const uint32_t stg = sb + (kt % 3) * AT_STAGE;
        const int k0 = kt * 64;

        // S = Q K^T (raw scores; alpha applied inside ex2)
        float s[8][4];
        #pragma unroll
        for (int i = 0; i < 8; i++)
            #pragma unroll
            for (int j = 0; j < 4; j++) s[i][j] = 0.f;
        #pragma unroll
        for (int ks = 0; ks < 4; ks++) {
            uint32_t kf_[8][2];
            #pragma unroll
            for (int g = 0; g < 4; g++)
                LDSM4(kf_[2*g][0], kf_[2*g][1], kf_[2*g+1][0], kf_[2*g+1][1],
                      stg + OF_K + (browbase + g * 16) * LDK + ks * 32 + bkadd);
            #pragma unroll
            for (int ni = 0; ni < 8; ni++)
                MMAH(s[ni], q[ks], kf_[ni]);
        }

        // causal mask (raw domain)
        if (k0 + 63 > q0 + wid * 16) {
            #pragma unroll
            for (int ni = 0; ni < 8; ni++) {
                int colg = k0 + ni * 8 + (lane & 3) * 2;
                if (colg     > rowg    ) s[ni][0] = -1e30f;
                if (colg + 1 > rowg    ) s[ni][1] = -1e30f;
                if (colg     > rowg + 8) s[ni][2] = -1e30f;
                if (colg + 1 > rowg + 8) s[ni][3] = -1e30f;
            }
        }

        // online softmax (max in raw domain)
        float mx0 = m0, mx1 = m1;
        #pragma unroll
        for (int ni = 0; ni < 8; ni++) {
            mx0 = fmaxf(mx0, fmaxf(s[ni][0], s[ni][1]));
            mx1 = fmaxf(mx1, fmaxf(s[ni][2], s[ni][3]));
        }
        mx0 = fmaxf(mx0, __shfl_xor_sync(0xffffffffu, mx0, 1));
        mx0 = fmaxf(mx0, __shfl_xor_sync(0xffffffffu, mx0, 2));
        mx1 = fmaxf(mx1, __shfl_xor_sync(0xffffffffu, mx1, 1));
        mx1 = fmaxf(mx1, __shfl_xor_sync(0xffffffffu, mx1, 2));

        // warp-vote rescale skip: if no lane's max grew, sc == 1 exactly
        if (__any_sync(0xffffffffu, (mx0 > m0) || (mx1 > m1))) {
            float sc0 = ex2f((m0 - mx0) * alpha);
            float sc1 = ex2f((m1 - mx1) * alpha);
            l0 *= sc0; l1 *= sc1;
            #pragma unroll
            for (int ni = 0; ni < 8; ni++) {
                o[ni][0] *= sc0; o[ni][1] *= sc0;
                o[ni][2] *= sc1; o[ni][3] *= sc1;
            }
            m0 = mx0; m1 = mx1;
        }
        const float mxa0 = m0 * alpha, mxa1 = m1 * alpha;

        // PV: P built per kf slice via single FFMA + ex2
        float rs0 = 0.f, rs1 = 0.f;
        #pragma unroll
        for (int kf = 0; kf < 4; kf++) {
            uint32_t p[4];
            #pragma unroll
            for (int j = 0; j < 2; j++) {
                int ni = 2 * kf + j;
                float p0 = ex2f(fmaf(s[ni][0], alpha, -mxa0));
                float p1 = ex2f(fmaf(s[ni][1], alpha, -mxa0));
                float p2 = ex2f(fmaf(s[ni][2], alpha, -mxa1));
                float p3 = ex2f(fmaf(s[ni][3], alpha, -mxa1));
                rs0 += p0 + p1; rs1 += p2 + p3;
                p[j * 2 + 0] = pack_h2(p0, p1);
                p[j * 2 + 1] = pack_h2(p2, p3);
            }
            uint32_t vf[8][2];
            #pragma unroll
            for (int g = 0; g < 4; g++)
                LDSM4T(vf[2*g][0], vf[2*g][1], vf[2*g+1][0], vf[2*g+1][1],
                       stg + OF_V + (kf * 16 + vrow) * LDK + g * 32 + vnadd);
            #pragma unroll
            for (int nd = 0; nd < 8; nd++)
                MMAH(o[nd], p, vf[nd]);
        }
        l0 += rs0; l1 += rs1;

        if (kt + 2 < nt) { issue_tile(kt + 2); CP_COMMIT(); }
    }

    // finalize
    l0 += __shfl_xor_sync(0xffffffffu, l0, 1);
    l0 += __shfl_xor_sync(0xffffffffu, l0, 2);
    l1 += __shfl_xor_sync(0xffffffffu, l1, 1);
    l1 += __shfl_xor_sync(0xffffffffu, l1, 2);
    const float inv0 = 1.f / l0, inv1 = 1.f / l1;

    // SMEM-staged coalesced Z write: 64 rows x 128 B (stride 144)
    __syncthreads();
    const int r0l = wid * 16 + (lane >> 2);
    #pragma unroll
    for (int nd = 0; nd < 8; nd++) {
        int col = nd * 8 + (lane & 3) * 2;
        *(uint32_t*)(sm + r0l * EPI_LDZ + col * 2) =
            pack_h2(o[nd][0] * inv0, o[nd][1] * inv0);
        *(uint32_t*)(sm + (r0l + 8) * EPI_LDZ + col * 2) =
            pack_h2(o[nd][2] * inv1, o[nd][3] * inv1);
    }
    __syncthreads();
    #pragma unroll
    for (int t = 0; t < 4; t++) {
        int idx = tid + t * 128;   // 0..511
        int row = idx >> 3, seg = idx & 7;
        *(uint4*)&Zh[hb + (size_t)(q0 + row) * HD_ + seg * 8] =
            *(uint4*)(sm + row * EPI_LDZ + seg * 16);
    }
}

// ---------------------------------------------------------------------------
// Launch
// ---------------------------------------------------------------------------
extern "C" void kernel_launch(void* const* d_in, const int* in_sizes, int n_in,
                              void* d_out, int out_size)
{
    const float* query = (const float*)d_in[0];
    const float* key_  = (const float*)d_in[1];
    const float* value = (const float*)d_in[2];
    const float* WQ = (const float*)d_in[4];
    const float* bQ = (const float*)d_in[5];
    const float* WK = (const float*)d_in[6];
    const float* bK = (const float*)d_in[7];
    const float* WV = (const float*)d_in[8];
    const float* bV = (const float*)d_in[9];
    const float* WO = (const float*)d_in[10];
    const float* bO = (const float*)d_in[11];
    float* out = (float*)d_out;

    __half *zh, *wt, *qh, *kh, *vh;
    cudaGetSymbolAddress((void**)&zh, g_Zh);
    cudaGetSymbolAddress((void**)&wt, g_Wt);
    cudaGetSymbolAddress((void**)&qh, g_Qh);
    cudaGetSymbolAddress((void**)&kh, g_Kh);
    cudaGetSymbolAddress((void**)&vh, g_Vh);

    PrepArgs pp;
    pp.W[0] = WQ; pp.W[1] = WK; pp.W[2] = WV; pp.W[3] = WO;

    QkvArgs qa;
    qa.A[0] = query; qa.A[1] = key_; qa.A[2] = value;
    qa.bias[0] = bQ; qa.bias[1] = bK; qa.bias[2] = bV;
    qa.O[0] = qh; qa.O[1] = kh; qa.O[2] = vh;

    const int GEMM_SMEM = NSTAGE * STAGE_B;   // 61440
    const int ATTN_SMEM = 3 * AT_STAGE;       // 55296
    cudaFuncSetAttribute(gemm_h_pipe<0>,
                         cudaFuncAttributeMaxDynamicSharedMemorySize, GEMM_SMEM);
    cudaFuncSetAttribute(gemm_h_pipe<1>,
                         cudaFuncAttributeMaxDynamicSharedMemorySize, GEMM_SMEM);
    cudaFuncSetAttribute(flash_attn_mma,
                         cudaFuncAttributeMaxDynamicSharedMemorySize, ATTN_SMEM);

    // 1. Weight prep only (inputs converted inline in gemm<0>)
    prep_w_kernel<<<4096, dim3(32, 8)>>>(pp, wt);

    // 2. QKV projections (one launch, grid.z = 3), fp32 A converted inline
    gemm_h_pipe<0><<<dim3(N_GEMM / 128, M_ / 128, 3), 256, GEMM_SMEM>>>(
        qa, nullptr, wt, nullptr, nullptr);

    // 3. Flash attention (64-row q-tiles, 4 CTAs/SM)
    flash_attn_mma<<<dim3(S_ / 64, H_, B_), 128, ATTN_SMEM>>>(
        qh, kh, vh, zh);

    // 4. Output projection -> fp32 out
    gemm_h_pipe<1><<<dim3(N_GEMM / 128, M_ / 128, 1), 256, GEMM_SMEM>>>(
        qa, zh, wt, bO, out);
}